// round 14
// baseline (speedup 1.0000x reference)
#include <cuda_runtime.h>
#include <cuda_bf16.h>
#include <cfloat>

#define KC 16
#define DC 64
#define NMAX 131072
#define CHUNK 256
#define NCHUNK_MAX (NMAX / CHUNK)
#define BW 4096
#define SLOTS 6144
#define BT 512

// ---------------- static device scratch ----------------
__device__ int   g_pred[NMAX];
__device__ int   g_ccx[NCHUNK_MAX * KC];
__device__ int   g_cct[NCHUNK_MAX * KC];
__device__ int   g_cbx[NCHUNK_MAX * KC];
__device__ int   g_cbt[NCHUNK_MAX * KC];
__device__ int   g_cntx[KC], g_cntt[KC];
__device__ float g_fillp[NCHUNK_MAX * KC];
__device__ float g_loss;
__device__ float g_bufx[2u * NMAX * DC];
__device__ float g_buft[2u * NMAX * DC];
__device__ unsigned g_scr[4u * NMAX * DC];   // slow-key overflow scratch

// normalized value bits: mantissa LSB := sign bit (<=1ulp perturbation)
__device__ __forceinline__ unsigned normBits(float f) {
    unsigned u = __float_as_uint(f);
    return (u & ~1u) | (u >> 31);
}
// sortable key from normalized bits (LSB ends up 0 -> free for tag)
__device__ __forceinline__ unsigned keyFromNorm(unsigned un) {
    return (un & 0x80000000u) ? ~un : (un | 0x80000000u);
}
__device__ __forceinline__ float decKey(unsigned key) {
    unsigned s = key & ~1u;
    unsigned u = (s & 0x80000000u) ? (s & 0x7fffffffu) : ~s;
    return __uint_as_float(u);
}

__device__ __forceinline__ int bucketOfNorm(unsigned un, float scale) {
    float v = __uint_as_float(un);
    int b = (int)((v + 6.f) * scale);
    return min(max(b, 0), BW - 1);
}

// in-block cluster geometry: m, pow2 pad, segment offset
__device__ __forceinline__ void computeOffsets(int* m16, int* p16, int* off16) {
    int tid = threadIdx.x;
    if (tid < 32) {
        int lane = tid;
        int m = 0, p = 0;
        if (lane < KC) {
            m = min(g_cntx[lane], g_cntt[lane]);
            p = (m <= 1) ? m : (1 << (32 - __clz(m - 1)));
        }
        int s = p;
        #pragma unroll
        for (int o = 1; o < 16; o <<= 1) {
            int y = __shfl_up_sync(0xffffffffu, s, o);
            if (lane >= o) s += y;
        }
        if (lane < KC) { m16[lane] = m; p16[lane] = p; off16[lane] = s - p; }
    }
    __syncthreads();
}

// ---------------- assignment + softmax filling + per-chunk counts ----------------
__global__ void assignK(const float* __restrict__ x, const float* __restrict__ C,
                        const int* __restrict__ pr, int N) {
    __shared__ float4 sC[KC * DC / 4];
    __shared__ float  sCC[KC];
    __shared__ float  sFill[KC];
    __shared__ int    sCnt[KC];
    __shared__ int    sCntT[KC];
    int tid = threadIdx.x;
    sC[tid] = ((const float4*)C)[tid];
    if (tid < KC) { sFill[tid] = 0.f; sCnt[tid] = 0; sCntT[tid] = 0; }
    __syncthreads();
    if (tid < KC) {
        float cc = 0.f;
        #pragma unroll
        for (int q = 0; q < DC / 4; q++) {
            float4 c = sC[tid * (DC / 4) + q];
            cc += c.x * c.x + c.y * c.y + c.z * c.z + c.w * c.w;
        }
        sCC[tid] = cc;
    }
    __syncthreads();

    int i = blockIdx.x * blockDim.x + tid;
    bool act = i < N;
    float sc[KC];
    int bk = 0;
    if (act) {
        atomicAdd(&sCntT[pr[i]], 1);
        float acc[KC];
        #pragma unroll
        for (int k = 0; k < KC; k++) acc[k] = 0.f;
        const float4* xr = (const float4*)(x + (size_t)i * DC);
        #pragma unroll
        for (int q = 0; q < DC / 4; q++) {
            float4 v = xr[q];
            #pragma unroll
            for (int k = 0; k < KC; k++) {
                float4 c = sC[k * (DC / 4) + q];
                acc[k] += v.x * c.x + v.y * c.y + v.z * c.z + v.w * c.w;
            }
        }
        float best = FLT_MAX;
        #pragma unroll
        for (int k = 0; k < KC; k++) {
            sc[k] = sCC[k] - 2.f * acc[k];
            if (sc[k] < best) { best = sc[k]; bk = k; }
        }
        g_pred[i] = bk;
        float sum = 0.f;
        #pragma unroll
        for (int k = 0; k < KC; k++) { float e = __expf(-4.f * (sc[k] - best)); sc[k] = e; sum += e; }
        float inv = 1.f / sum;
        #pragma unroll
        for (int k = 0; k < KC; k++) sc[k] *= inv;
        atomicAdd(&sCnt[bk], 1);
    } else {
        #pragma unroll
        for (int k = 0; k < KC; k++) sc[k] = 0.f;
    }
    int lane = tid & 31;
    #pragma unroll
    for (int k = 0; k < KC; k++) {
        float v = sc[k];
        v += __shfl_down_sync(0xffffffffu, v, 16);
        v += __shfl_down_sync(0xffffffffu, v, 8);
        v += __shfl_down_sync(0xffffffffu, v, 4);
        v += __shfl_down_sync(0xffffffffu, v, 2);
        v += __shfl_down_sync(0xffffffffu, v, 1);
        if (lane == 0) atomicAdd(&sFill[k], v);
    }
    __syncthreads();
    if (tid < KC) {
        g_ccx[blockIdx.x * KC + tid] = sCnt[tid];
        g_cct[blockIdx.x * KC + tid] = sCntT[tid];
        g_fillp[blockIdx.x * KC + tid] = sFill[tid];
    }
}

// ---------------- parallel chunk-base scan; zeroes g_loss ----------------
__global__ void scanAK(int nchunk) {
    int b = blockIdx.x;
    int k = b & 15;
    const int* cc = (b < 16) ? g_ccx : g_cct;
    int* cb       = (b < 16) ? g_cbx : g_cbt;
    __shared__ int wtmp[16];
    int tid = threadIdx.x, lane = tid & 31, wid = tid >> 5;
    if (b == 0 && tid == 0) g_loss = 0.f;
    int run = 0;
    for (int c0 = 0; c0 < nchunk; c0 += blockDim.x) {
        int c = c0 + tid;
        int v = (c < nchunk) ? cc[c * KC + k] : 0;
        int s = v;
        #pragma unroll
        for (int o = 1; o < 32; o <<= 1) {
            int y = __shfl_up_sync(0xffffffffu, s, o);
            if (lane >= o) s += y;
        }
        if (lane == 31) wtmp[wid] = s;
        __syncthreads();
        if (wid == 0) {
            int a = (lane < 16) ? wtmp[lane] : 0;
            #pragma unroll
            for (int o = 1; o < 16; o <<= 1) {
                int y = __shfl_up_sync(0xffffffffu, a, o);
                if (lane >= o) a += y;
            }
            if (lane < 16) wtmp[lane] = a;
        }
        __syncthreads();
        int base = (wid ? wtmp[wid - 1] : 0);
        int tot = wtmp[15];
        if (c < nchunk) cb[c * KC + k] = run + base + s - v;
        run += tot;
        __syncthreads();
    }
    if (tid == 0) { if (b < 16) g_cntx[k] = run; else g_cntt[k] = run; }
}

// ---------------- stable scatter (both sources via blockIdx.y) ----------------
__global__ void scatterK(const float* __restrict__ x, const float* __restrict__ tg,
                         const int* __restrict__ pr, int N) {
    __shared__ int wcnt[8][KC];
    __shared__ int m16[KC], p16[KC], off16[KC];
    computeOffsets(m16, p16, off16);
    int isx = (blockIdx.y == 0);
    const float* src = isx ? x : tg;
    const int* pred  = isx ? g_pred : pr;
    const int* cb    = isx ? g_cbx : g_cbt;
    float* dst       = isx ? g_bufx : g_buft;
    int tid = threadIdx.x;
    if (tid < 8 * KC) ((int*)wcnt)[tid] = 0;
    __syncthreads();
    int i = blockIdx.x * blockDim.x + tid;
    int lane = tid & 31, w = tid >> 5;
    int k = 0, lr = 0;
    bool act = i < N;
    unsigned ball = __ballot_sync(0xffffffffu, act);
    if (act) {
        k = pred[i];
        unsigned mm = __match_any_sync(ball, k);
        lr = __popc(mm & ((1u << lane) - 1u));
        if (lane == (int)(__ffs(mm) - 1)) wcnt[w][k] = __popc(mm);
    }
    __syncthreads();
    if (act) {
        int base = cb[blockIdx.x * KC + k];
        #pragma unroll
        for (int ww = 0; ww < 8; ww++)
            if (ww < w) base += wcnt[ww][k];
        int r = base + lr;
        int m = m16[k];
        if (r < m) {
            int P = p16[k];
            float* buf = dst + (size_t)off16[k] * DC + r;
            const float4* s4 = (const float4*)(src + (size_t)i * DC);
            #pragma unroll
            for (int q = 0; q < DC / 4; q++) {
                float4 v = s4[q];
                buf[(size_t)(4 * q + 0) * P] = v.x;
                buf[(size_t)(4 * q + 1) * P] = v.y;
                buf[(size_t)(4 * q + 2) * P] = v.z;
                buf[(size_t)(4 * q + 3) * P] = v.w;
            }
        }
    }
}

// ==================== unified bucket fast/slow W1 ====================

template <int NT, int PER>
__device__ __forceinline__ int scanExInPlace(int* arr, int* wtmp) {
    constexpr int NW = NT / 32;
    int tid = threadIdx.x, lane = tid & 31, wid = tid >> 5;
    int v[PER];
    #pragma unroll
    for (int j = 0; j < PER; j++) v[j] = arr[tid * PER + j];
    int sum = 0;
    #pragma unroll
    for (int j = 0; j < PER; j++) { int t = v[j]; v[j] = sum; sum += t; }
    int inc = sum;
    #pragma unroll
    for (int o = 1; o < 32; o <<= 1) {
        int y = __shfl_up_sync(0xffffffffu, inc, o);
        if (lane >= o) inc += y;
    }
    if (lane == 31) wtmp[wid] = inc;
    __syncthreads();
    if (wid == 0) {
        int a = (lane < NW) ? wtmp[lane] : 0;
        #pragma unroll
        for (int o = 1; o < 32; o <<= 1) {
            int y = __shfl_up_sync(0xffffffffu, a, o);
            if (lane >= o) a += y;
        }
        if (lane < NW) wtmp[lane] = a;
    }
    __syncthreads();
    int base = (wid ? wtmp[wid - 1] : 0) + inc - sum;
    int total = wtmp[NW - 1];
    __syncthreads();
    #pragma unroll
    for (int j = 0; j < PER; j++) arr[tid * PER + j] = base + v[j];
    return total;
}

__global__ void __launch_bounds__(BT) wassU() {
    __shared__ int m16[KC], p16[KC], off16[KC];
    __shared__ int wtmp[32];
    __shared__ float redtmp[32];
    computeOffsets(m16, p16, off16);

    int seg = blockIdx.x;
    int k = seg & 15, d = seg >> 4;     // interleave cluster sizes across waves
    int m = m16[k];
    if (m <= 0) return;
    int twoM = 2 * m;
    int P = p16[k];
    const float* bx = g_bufx + (size_t)off16[k] * DC + (size_t)d * P;
    const float* bt = g_buft + (size_t)off16[k] * DC + (size_t)d * P;

    extern __shared__ __align__(16) int sm[];
    int* cntA = sm;
    int* run0 = sm + BW;
    int* S1   = sm + 2 * BW;
    unsigned* skeys = (unsigned*)(sm + 3 * BW);

    int tid = threadIdx.x;
    const float scale = (float)BW / 12.f;

    for (int b = tid; b < BW; b += BT) { cntA[b] = 0; run0[b] = 0; }
    __syncthreads();

    int m4 = ((P & 3) == 0) ? (m & ~3) : 0;

    // ---------- phase 1: histogram (count + signed), float4 loads ----------
    for (int i = tid * 4; i < m4; i += BT * 4) {
        float4 f = *(const float4*)(bx + i);
        int b0 = bucketOfNorm(normBits(f.x), scale);
        int b1 = bucketOfNorm(normBits(f.y), scale);
        int b2 = bucketOfNorm(normBits(f.z), scale);
        int b3 = bucketOfNorm(normBits(f.w), scale);
        atomicAdd(&cntA[b0], 1); atomicAdd(&run0[b0], 1);
        atomicAdd(&cntA[b1], 1); atomicAdd(&run0[b1], 1);
        atomicAdd(&cntA[b2], 1); atomicAdd(&run0[b2], 1);
        atomicAdd(&cntA[b3], 1); atomicAdd(&run0[b3], 1);
    }
    for (int i = m4 + tid; i < m; i += BT) {
        int b = bucketOfNorm(normBits(bx[i]), scale);
        atomicAdd(&cntA[b], 1); atomicAdd(&run0[b], 1);
    }
    for (int i = tid * 4; i < m4; i += BT * 4) {
        float4 f = *(const float4*)(bt + i);
        int b0 = bucketOfNorm(normBits(f.x), scale);
        int b1 = bucketOfNorm(normBits(f.y), scale);
        int b2 = bucketOfNorm(normBits(f.z), scale);
        int b3 = bucketOfNorm(normBits(f.w), scale);
        atomicAdd(&cntA[b0], 1); atomicAdd(&run0[b0], -1);
        atomicAdd(&cntA[b1], 1); atomicAdd(&run0[b1], -1);
        atomicAdd(&cntA[b2], 1); atomicAdd(&run0[b2], -1);
        atomicAdd(&cntA[b3], 1); atomicAdd(&run0[b3], -1);
    }
    for (int i = m4 + tid; i < m; i += BT) {
        int b = bucketOfNorm(normBits(bt[i]), scale);
        atomicAdd(&cntA[b], 1); atomicAdd(&run0[b], -1);
    }
    __syncthreads();
    scanExInPlace<BT, BW / BT>(run0, wtmp);
    __syncthreads();

    // slow-bucket compact offsets
    for (int b = tid; b < BW; b += BT) {
        int cnt = cntA[b];
        int r0 = run0[b];
        S1[b] = (r0 <= cnt && r0 >= -cnt) ? cnt : 0;
    }
    __syncthreads();
    int S = scanExInPlace<BT, BW / BT>(S1, wtmp);
    __syncthreads();

    unsigned* kbuf = (S <= SLOTS) ? skeys
                   : (g_scr + (size_t)off16[k] * 2 * DC + (size_t)d * 2 * P);

    // ---------- phase 2: fast items emit +-v; slow items compact-scatter ----------
    float acc = 0.f;
    for (int i = tid * 4; i < m4; i += BT * 4) {
        float4 f = *(const float4*)(bx + i);
        {
            unsigned un = normBits(f.x);
            int b = bucketOfNorm(un, scale);
            int cnt = cntA[b], r0 = run0[b];
            float v = __uint_as_float(un);
            if (r0 > cnt) acc -= v;
            else if (r0 < -cnt) acc += v;
            else { int pos = atomicAdd(&S1[b], 1); kbuf[pos] = keyFromNorm(un) | 1u; }
        }
        {
            unsigned un = normBits(f.y);
            int b = bucketOfNorm(un, scale);
            int cnt = cntA[b], r0 = run0[b];
            float v = __uint_as_float(un);
            if (r0 > cnt) acc -= v;
            else if (r0 < -cnt) acc += v;
            else { int pos = atomicAdd(&S1[b], 1); kbuf[pos] = keyFromNorm(un) | 1u; }
        }
        {
            unsigned un = normBits(f.z);
            int b = bucketOfNorm(un, scale);
            int cnt = cntA[b], r0 = run0[b];
            float v = __uint_as_float(un);
            if (r0 > cnt) acc -= v;
            else if (r0 < -cnt) acc += v;
            else { int pos = atomicAdd(&S1[b], 1); kbuf[pos] = keyFromNorm(un) | 1u; }
        }
        {
            unsigned un = normBits(f.w);
            int b = bucketOfNorm(un, scale);
            int cnt = cntA[b], r0 = run0[b];
            float v = __uint_as_float(un);
            if (r0 > cnt) acc -= v;
            else if (r0 < -cnt) acc += v;
            else { int pos = atomicAdd(&S1[b], 1); kbuf[pos] = keyFromNorm(un) | 1u; }
        }
    }
    for (int i = m4 + tid; i < m; i += BT) {
        unsigned un = normBits(bx[i]);
        int b = bucketOfNorm(un, scale);
        int cnt = cntA[b], r0 = run0[b];
        float v = __uint_as_float(un);
        if (r0 > cnt) acc -= v;
        else if (r0 < -cnt) acc += v;
        else { int pos = atomicAdd(&S1[b], 1); kbuf[pos] = keyFromNorm(un) | 1u; }
    }
    for (int i = tid * 4; i < m4; i += BT * 4) {
        float4 f = *(const float4*)(bt + i);
        {
            unsigned un = normBits(f.x);
            int b = bucketOfNorm(un, scale);
            int cnt = cntA[b], r0 = run0[b];
            float v = __uint_as_float(un);
            if (r0 > cnt) acc += v;
            else if (r0 < -cnt) acc -= v;
            else { int pos = atomicAdd(&S1[b], 1); kbuf[pos] = keyFromNorm(un); }
        }
        {
            unsigned un = normBits(f.y);
            int b = bucketOfNorm(un, scale);
            int cnt = cntA[b], r0 = run0[b];
            float v = __uint_as_float(un);
            if (r0 > cnt) acc += v;
            else if (r0 < -cnt) acc -= v;
            else { int pos = atomicAdd(&S1[b], 1); kbuf[pos] = keyFromNorm(un); }
        }
        {
            unsigned un = normBits(f.z);
            int b = bucketOfNorm(un, scale);
            int cnt = cntA[b], r0 = run0[b];
            float v = __uint_as_float(un);
            if (r0 > cnt) acc += v;
            else if (r0 < -cnt) acc -= v;
            else { int pos = atomicAdd(&S1[b], 1); kbuf[pos] = keyFromNorm(un); }
        }
        {
            unsigned un = normBits(f.w);
            int b = bucketOfNorm(un, scale);
            int cnt = cntA[b], r0 = run0[b];
            float v = __uint_as_float(un);
            if (r0 > cnt) acc += v;
            else if (r0 < -cnt) acc -= v;
            else { int pos = atomicAdd(&S1[b], 1); kbuf[pos] = keyFromNorm(un); }
        }
    }
    for (int i = m4 + tid; i < m; i += BT) {
        unsigned un = normBits(bt[i]);
        int b = bucketOfNorm(un, scale);
        int cnt = cntA[b], r0 = run0[b];
        float v = __uint_as_float(un);
        if (r0 > cnt) acc += v;
        else if (r0 < -cnt) acc -= v;
        else { int pos = atomicAdd(&S1[b], 1); kbuf[pos] = keyFromNorm(un); }
    }
    __syncthreads();

    // ---------- phase 3: resolve slow items within their bucket ----------
    for (int idx = tid; idx < S; idx += BT) {
        unsigned kk = kbuf[idx];
        float v = decKey(kk);
        int b = bucketOfNorm(__float_as_uint(v), scale);
        int en = S1[b];
        int cnt = cntA[b];
        int st = en - cnt;
        int run = run0[b];
        int mytag = (kk & 1u) ? 1 : -1;
        for (int j = st; j < en; j++) {
            unsigned kj = kbuf[j];
            bool le = (kj < kk) || (kj == kk && j <= idx);
            if (le) run += (kj & 1u) ? 1 : -1;
        }
        acc += v * (fabsf((float)(run - mytag)) - fabsf((float)run));
    }
    __syncthreads();

    // block reduce + accumulate
    int lane = tid & 31, wid = tid >> 5;
    #pragma unroll
    for (int o = 16; o; o >>= 1) acc += __shfl_down_sync(0xffffffffu, acc, o);
    if (lane == 0) redtmp[wid] = acc;
    __syncthreads();
    if (wid == 0) {
        float t = (lane < BT / 32) ? redtmp[lane] : 0.f;
        #pragma unroll
        for (int o = 16; o; o >>= 1) t += __shfl_down_sync(0xffffffffu, t, o);
        if (lane == 0) atomicAdd(&g_loss, t / ((float)m * (float)DC));
    }
}

// ---------------- finalize: reduce fill partials + combine ----------------
__global__ void finalK(const float* __restrict__ ft, float* __restrict__ out,
                       int N, int nchunk) {
    __shared__ float red[256];
    int tid = threadIdx.x;
    int k = tid & 15, g = tid >> 4;
    float s = 0.f;
    for (int c = g; c < nchunk; c += 16) s += g_fillp[c * KC + k];
    red[tid] = s;
    __syncthreads();
    for (int o = 128; o >= 16; o >>= 1) {
        if (tid < o) red[tid] += red[tid + o];
        __syncthreads();
    }
    if (tid == 0) {
        float lf = 0.f;
        for (int kk = 0; kk < KC; kk++) {
            float df = red[kk] / (float)N - ft[kk];
            lf += df * df;
        }
        out[0] = g_loss + lf / (float)KC;
    }
}

extern "C" void kernel_launch(void* const* d_in, const int* in_sizes, int n_in,
                              void* d_out, int out_size) {
    const float* x  = (const float*)d_in[0];
    const float* C  = (const float*)d_in[1];
    const float* ft = (const float*)d_in[2];
    const float* tg = (const float*)d_in[3];
    const int*   pr = (const int*)d_in[4];
    float* out = (float*)d_out;
    int N = in_sizes[0] / DC;
    int nblk = (N + CHUNK - 1) / CHUNK;

    size_t sw = (size_t)(3 * BW + SLOTS) * 4;   // 72 KB -> 3 blocks/SM
    cudaFuncSetAttribute(wassU, cudaFuncAttributeMaxDynamicSharedMemorySize, (int)sw);

    assignK<<<nblk, 256>>>(x, C, pr, N);
    scanAK<<<32, 512>>>(nblk);
    scatterK<<<dim3(nblk, 2), 256>>>(x, tg, pr, N);
    wassU<<<KC * DC, BT, sw>>>();
    finalK<<<1, 256>>>(ft, out, N, nblk);
}

// round 15
// speedup vs baseline: 2.0902x; 2.0902x over previous
#include <cuda_runtime.h>
#include <cuda_bf16.h>
#include <cfloat>

#define KC 16
#define DC 64
#define NMAX 131072
#define CHUNK 256
#define NCHUNK_MAX (NMAX / CHUNK)
#define BW 8192
#define SLOTS 4096
#define BT 512

// ---------------- static device scratch ----------------
__device__ int   g_pred[NMAX];
__device__ int   g_ccx[NCHUNK_MAX * KC];
__device__ int   g_cct[NCHUNK_MAX * KC];
__device__ int   g_cbx[NCHUNK_MAX * KC];
__device__ int   g_cbt[NCHUNK_MAX * KC];
__device__ int   g_cntx[KC], g_cntt[KC];
__device__ float g_fillp[NCHUNK_MAX * KC];
__device__ float g_loss;
__device__ float g_bufx[2u * NMAX * DC];
__device__ float g_buft[2u * NMAX * DC];
__device__ unsigned g_scr[4u * NMAX * DC];   // slow-key overflow scratch

// sortable-uint encode with LSB reserved for source tag (<=1ulp perturbation)
__device__ __forceinline__ unsigned encKey(float f) {
    unsigned u = __float_as_uint(f);
    unsigned s = (u & 0x80000000u) ? ~u : (u | 0x80000000u);
    return s & ~1u;
}
__device__ __forceinline__ float decKey(unsigned key) {
    unsigned s = key & ~1u;
    unsigned u = (s & 0x80000000u) ? (s & 0x7fffffffu) : ~s;
    return __uint_as_float(u);
}

// in-block cluster geometry: m, pow2 pad, segment offset
__device__ __forceinline__ void computeOffsets(int* m16, int* p16, int* off16) {
    int tid = threadIdx.x;
    if (tid < 32) {
        int lane = tid;
        int m = 0, p = 0;
        if (lane < KC) {
            m = min(g_cntx[lane], g_cntt[lane]);
            p = (m <= 1) ? m : (1 << (32 - __clz(m - 1)));
        }
        int s = p;
        #pragma unroll
        for (int o = 1; o < 16; o <<= 1) {
            int y = __shfl_up_sync(0xffffffffu, s, o);
            if (lane >= o) s += y;
        }
        if (lane < KC) { m16[lane] = m; p16[lane] = p; off16[lane] = s - p; }
    }
    __syncthreads();
}

// ---------------- assignment + softmax filling + per-chunk counts ----------------
__global__ void assignK(const float* __restrict__ x, const float* __restrict__ C,
                        const int* __restrict__ pr, int N) {
    __shared__ float4 sC[KC * DC / 4];
    __shared__ float  sCC[KC];
    __shared__ float  sFill[KC];
    __shared__ int    sCnt[KC];
    __shared__ int    sCntT[KC];
    int tid = threadIdx.x;
    sC[tid] = ((const float4*)C)[tid];
    if (tid < KC) { sFill[tid] = 0.f; sCnt[tid] = 0; sCntT[tid] = 0; }
    __syncthreads();
    if (tid < KC) {
        float cc = 0.f;
        #pragma unroll
        for (int q = 0; q < DC / 4; q++) {
            float4 c = sC[tid * (DC / 4) + q];
            cc += c.x * c.x + c.y * c.y + c.z * c.z + c.w * c.w;
        }
        sCC[tid] = cc;
    }
    __syncthreads();

    int i = blockIdx.x * blockDim.x + tid;
    bool act = i < N;
    float sc[KC];
    int bk = 0;
    if (act) {
        atomicAdd(&sCntT[pr[i]], 1);
        float acc[KC];
        #pragma unroll
        for (int k = 0; k < KC; k++) acc[k] = 0.f;
        const float4* xr = (const float4*)(x + (size_t)i * DC);
        #pragma unroll
        for (int q = 0; q < DC / 4; q++) {
            float4 v = xr[q];
            #pragma unroll
            for (int k = 0; k < KC; k++) {
                float4 c = sC[k * (DC / 4) + q];
                acc[k] += v.x * c.x + v.y * c.y + v.z * c.z + v.w * c.w;
            }
        }
        float best = FLT_MAX;
        #pragma unroll
        for (int k = 0; k < KC; k++) {
            sc[k] = sCC[k] - 2.f * acc[k];
            if (sc[k] < best) { best = sc[k]; bk = k; }
        }
        g_pred[i] = bk;
        float sum = 0.f;
        #pragma unroll
        for (int k = 0; k < KC; k++) { float e = __expf(-4.f * (sc[k] - best)); sc[k] = e; sum += e; }
        float inv = 1.f / sum;
        #pragma unroll
        for (int k = 0; k < KC; k++) sc[k] *= inv;
        atomicAdd(&sCnt[bk], 1);
    } else {
        #pragma unroll
        for (int k = 0; k < KC; k++) sc[k] = 0.f;
    }
    int lane = tid & 31;
    #pragma unroll
    for (int k = 0; k < KC; k++) {
        float v = sc[k];
        v += __shfl_down_sync(0xffffffffu, v, 16);
        v += __shfl_down_sync(0xffffffffu, v, 8);
        v += __shfl_down_sync(0xffffffffu, v, 4);
        v += __shfl_down_sync(0xffffffffu, v, 2);
        v += __shfl_down_sync(0xffffffffu, v, 1);
        if (lane == 0) atomicAdd(&sFill[k], v);
    }
    __syncthreads();
    if (tid < KC) {
        g_ccx[blockIdx.x * KC + tid] = sCnt[tid];
        g_cct[blockIdx.x * KC + tid] = sCntT[tid];
        g_fillp[blockIdx.x * KC + tid] = sFill[tid];
    }
}

// ---------------- parallel chunk-base scan; zeroes g_loss ----------------
__global__ void scanAK(int nchunk) {
    int b = blockIdx.x;
    int k = b & 15;
    const int* cc = (b < 16) ? g_ccx : g_cct;
    int* cb       = (b < 16) ? g_cbx : g_cbt;
    __shared__ int wtmp[16];
    int tid = threadIdx.x, lane = tid & 31, wid = tid >> 5;
    if (b == 0 && tid == 0) g_loss = 0.f;
    int run = 0;
    for (int c0 = 0; c0 < nchunk; c0 += blockDim.x) {
        int c = c0 + tid;
        int v = (c < nchunk) ? cc[c * KC + k] : 0;
        int s = v;
        #pragma unroll
        for (int o = 1; o < 32; o <<= 1) {
            int y = __shfl_up_sync(0xffffffffu, s, o);
            if (lane >= o) s += y;
        }
        if (lane == 31) wtmp[wid] = s;
        __syncthreads();
        if (wid == 0) {
            int a = (lane < 16) ? wtmp[lane] : 0;
            #pragma unroll
            for (int o = 1; o < 16; o <<= 1) {
                int y = __shfl_up_sync(0xffffffffu, a, o);
                if (lane >= o) a += y;
            }
            if (lane < 16) wtmp[lane] = a;
        }
        __syncthreads();
        int base = (wid ? wtmp[wid - 1] : 0);
        int tot = wtmp[15];
        if (c < nchunk) cb[c * KC + k] = run + base + s - v;
        run += tot;
        __syncthreads();
    }
    if (tid == 0) { if (b < 16) g_cntx[k] = run; else g_cntt[k] = run; }
}

// ---------------- stable scatter (both sources via blockIdx.y) ----------------
__global__ void scatterK(const float* __restrict__ x, const float* __restrict__ tg,
                         const int* __restrict__ pr, int N) {
    __shared__ int wcnt[8][KC];
    __shared__ int m16[KC], p16[KC], off16[KC];
    computeOffsets(m16, p16, off16);
    int isx = (blockIdx.y == 0);
    const float* src = isx ? x : tg;
    const int* pred  = isx ? g_pred : pr;
    const int* cb    = isx ? g_cbx : g_cbt;
    float* dst       = isx ? g_bufx : g_buft;
    int tid = threadIdx.x;
    if (tid < 8 * KC) ((int*)wcnt)[tid] = 0;
    __syncthreads();
    int i = blockIdx.x * blockDim.x + tid;
    int lane = tid & 31, w = tid >> 5;
    int k = 0, lr = 0;
    bool act = i < N;
    unsigned ball = __ballot_sync(0xffffffffu, act);
    if (act) {
        k = pred[i];
        unsigned mm = __match_any_sync(ball, k);
        lr = __popc(mm & ((1u << lane) - 1u));
        if (lane == (int)(__ffs(mm) - 1)) wcnt[w][k] = __popc(mm);
    }
    __syncthreads();
    if (act) {
        int base = cb[blockIdx.x * KC + k];
        #pragma unroll
        for (int ww = 0; ww < 8; ww++)
            if (ww < w) base += wcnt[ww][k];
        int r = base + lr;
        int m = m16[k];
        if (r < m) {
            int P = p16[k];
            float* buf = dst + (size_t)off16[k] * DC + r;
            const float4* s4 = (const float4*)(src + (size_t)i * DC);
            #pragma unroll
            for (int q = 0; q < DC / 4; q++) {
                float4 v = s4[q];
                buf[(size_t)(4 * q + 0) * P] = v.x;
                buf[(size_t)(4 * q + 1) * P] = v.y;
                buf[(size_t)(4 * q + 2) * P] = v.z;
                buf[(size_t)(4 * q + 3) * P] = v.w;
            }
        }
    }
}

// ==================== unified bucket fast/slow W1 (R10 body, BW=8192) ====================

template <int NT, int PER>
__device__ __forceinline__ int scanExInPlace(int* arr, int* wtmp) {
    constexpr int NW = NT / 32;
    int tid = threadIdx.x, lane = tid & 31, wid = tid >> 5;
    int v[PER];
    #pragma unroll
    for (int j = 0; j < PER; j++) v[j] = arr[tid * PER + j];
    int sum = 0;
    #pragma unroll
    for (int j = 0; j < PER; j++) { int t = v[j]; v[j] = sum; sum += t; }
    int inc = sum;
    #pragma unroll
    for (int o = 1; o < 32; o <<= 1) {
        int y = __shfl_up_sync(0xffffffffu, inc, o);
        if (lane >= o) inc += y;
    }
    if (lane == 31) wtmp[wid] = inc;
    __syncthreads();
    if (wid == 0) {
        int a = (lane < NW) ? wtmp[lane] : 0;
        #pragma unroll
        for (int o = 1; o < 32; o <<= 1) {
            int y = __shfl_up_sync(0xffffffffu, a, o);
            if (lane >= o) a += y;
        }
        if (lane < NW) wtmp[lane] = a;
    }
    __syncthreads();
    int base = (wid ? wtmp[wid - 1] : 0) + inc - sum;
    int total = wtmp[NW - 1];
    __syncthreads();
    #pragma unroll
    for (int j = 0; j < PER; j++) arr[tid * PER + j] = base + v[j];
    return total;
}

__global__ void __launch_bounds__(BT) wassU() {
    __shared__ int m16[KC], p16[KC], off16[KC];
    __shared__ int wtmp[32];
    __shared__ float redtmp[32];
    computeOffsets(m16, p16, off16);

    int seg = blockIdx.x;
    int k = seg & 15, d = seg >> 4;     // interleave cluster sizes across waves
    int m = m16[k];
    if (m <= 0) return;
    int twoM = 2 * m;
    int P = p16[k];
    const float* bx = g_bufx + (size_t)off16[k] * DC + (size_t)d * P;
    const float* bt = g_buft + (size_t)off16[k] * DC + (size_t)d * P;

    extern __shared__ __align__(16) int sm[];
    int* cntA = sm;
    int* run0 = sm + BW;
    int* S1   = sm + 2 * BW;
    unsigned* skeys = (unsigned*)(sm + 3 * BW);

    int tid = threadIdx.x;
    const float scale = (float)BW / 12.f;

    for (int b = tid; b < BW; b += BT) { cntA[b] = 0; run0[b] = 0; }
    __syncthreads();

    // phase 1: histogram (count + signed)
    for (int i = tid; i < twoM; i += BT) {
        unsigned key = (i < m) ? (encKey(bx[i]) | 1u) : encKey(bt[i - m]);
        float v = decKey(key);
        int b = min(max((int)((v + 6.f) * scale), 0), BW - 1);
        atomicAdd(&cntA[b], 1);
        atomicAdd(&run0[b], (key & 1u) ? 1 : -1);
    }
    __syncthreads();
    scanExInPlace<BT, BW / BT>(run0, wtmp);
    __syncthreads();

    // slow-bucket compact offsets
    for (int b = tid; b < BW; b += BT) {
        int cnt = cntA[b];
        int r0 = run0[b];
        S1[b] = (r0 <= cnt && r0 >= -cnt) ? cnt : 0;
    }
    __syncthreads();
    int S = scanExInPlace<BT, BW / BT>(S1, wtmp);
    __syncthreads();

    unsigned* kbuf = (S <= SLOTS) ? skeys
                   : (g_scr + (size_t)off16[k] * 2 * DC + (size_t)d * 2 * P);

    // phase 2: fast items emit +-v; slow items compact-scatter
    float acc = 0.f;
    for (int i = tid; i < twoM; i += BT) {
        unsigned key = (i < m) ? (encKey(bx[i]) | 1u) : encKey(bt[i - m]);
        float v = decKey(key);
        int b = min(max((int)((v + 6.f) * scale), 0), BW - 1);
        int cnt = cntA[b];
        int r0 = run0[b];
        float tv = (key & 1u) ? v : -v;
        if (r0 > cnt)       acc -= tv;
        else if (r0 < -cnt) acc += tv;
        else {
            int pos = atomicAdd(&S1[b], 1);
            kbuf[pos] = key;
        }
    }
    __syncthreads();

    // phase 3: resolve slow items within their bucket
    for (int idx = tid; idx < S; idx += BT) {
        unsigned kk = kbuf[idx];
        float v = decKey(kk);
        int b = min(max((int)((v + 6.f) * scale), 0), BW - 1);
        int en = S1[b];
        int cnt = cntA[b];
        int st = en - cnt;
        int run = run0[b];
        int mytag = (kk & 1u) ? 1 : -1;
        for (int j = st; j < en; j++) {
            unsigned kj = kbuf[j];
            bool le = (kj < kk) || (kj == kk && j <= idx);
            if (le) run += (kj & 1u) ? 1 : -1;
        }
        acc += v * (fabsf((float)(run - mytag)) - fabsf((float)run));
    }
    __syncthreads();

    // block reduce + accumulate
    int lane = tid & 31, wid = tid >> 5;
    #pragma unroll
    for (int o = 16; o; o >>= 1) acc += __shfl_down_sync(0xffffffffu, acc, o);
    if (lane == 0) redtmp[wid] = acc;
    __syncthreads();
    if (wid == 0) {
        float t = (lane < BT / 32) ? redtmp[lane] : 0.f;
        #pragma unroll
        for (int o = 16; o; o >>= 1) t += __shfl_down_sync(0xffffffffu, t, o);
        if (lane == 0) atomicAdd(&g_loss, t / ((float)m * (float)DC));
    }
}

// ---------------- finalize: reduce fill partials + combine ----------------
__global__ void finalK(const float* __restrict__ ft, float* __restrict__ out,
                       int N, int nchunk) {
    __shared__ float red[256];
    int tid = threadIdx.x;
    int k = tid & 15, g = tid >> 4;
    float s = 0.f;
    for (int c = g; c < nchunk; c += 16) s += g_fillp[c * KC + k];
    red[tid] = s;
    __syncthreads();
    for (int o = 128; o >= 16; o >>= 1) {
        if (tid < o) red[tid] += red[tid + o];
        __syncthreads();
    }
    if (tid == 0) {
        float lf = 0.f;
        for (int kk = 0; kk < KC; kk++) {
            float df = red[kk] / (float)N - ft[kk];
            lf += df * df;
        }
        out[0] = g_loss + lf / (float)KC;
    }
}

extern "C" void kernel_launch(void* const* d_in, const int* in_sizes, int n_in,
                              void* d_out, int out_size) {
    const float* x  = (const float*)d_in[0];
    const float* C  = (const float*)d_in[1];
    const float* ft = (const float*)d_in[2];
    const float* tg = (const float*)d_in[3];
    const int*   pr = (const int*)d_in[4];
    float* out = (float*)d_out;
    int N = in_sizes[0] / DC;
    int nblk = (N + CHUNK - 1) / CHUNK;

    size_t sw = (size_t)(3 * BW + SLOTS) * 4;   // 112 KB -> 2 blocks/SM
    cudaFuncSetAttribute(wassU, cudaFuncAttributeMaxDynamicSharedMemorySize, (int)sw);

    assignK<<<nblk, 256>>>(x, C, pr, N);
    scanAK<<<32, 512>>>(nblk);
    scatterK<<<dim3(nblk, 2), 256>>>(x, tg, pr, N);
    wassU<<<KC * DC, BT, sw>>>();
    finalK<<<1, 256>>>(ft, out, N, nblk);
}

// round 16
// speedup vs baseline: 2.1663x; 1.0364x over previous
#include <cuda_runtime.h>
#include <cuda_bf16.h>
#include <cfloat>

#define KC 16
#define DC 64
#define NMAX 131072
#define CHUNK 256
#define NCHUNK_MAX (NMAX / CHUNK)
#define BW 8192
#define SLOTS 4096
#define BT 512

// ---------------- static device scratch ----------------
__device__ int   g_pred[NMAX];
__device__ int   g_ccx[NCHUNK_MAX * KC];
__device__ int   g_cct[NCHUNK_MAX * KC];
__device__ int   g_cbx[NCHUNK_MAX * KC];
__device__ int   g_cbt[NCHUNK_MAX * KC];
__device__ int   g_cntx[KC], g_cntt[KC];
__device__ float g_fillp[NCHUNK_MAX * KC];
__device__ float g_loss;
__device__ float g_bufx[2u * NMAX * DC];
__device__ float g_buft[2u * NMAX * DC];
__device__ unsigned g_scr[4u * NMAX * DC];   // slow-key overflow scratch

// normalized value bits: mantissa LSB := sign bit (<=1ulp perturbation)
__device__ __forceinline__ unsigned normBits(float f) {
    unsigned u = __float_as_uint(f);
    return (u & ~1u) | (u >> 31);
}
// sortable key from normalized bits (LSB ends up 0 -> free for tag)
__device__ __forceinline__ unsigned keyFromNorm(unsigned un) {
    return (un & 0x80000000u) ? ~un : (un | 0x80000000u);
}
__device__ __forceinline__ float decKey(unsigned key) {
    unsigned s = key & ~1u;
    unsigned u = (s & 0x80000000u) ? (s & 0x7fffffffu) : ~s;
    return __uint_as_float(u);
}
__device__ __forceinline__ int bucketOfBits(unsigned un, float scale) {
    float v = __uint_as_float(un);
    int b = (int)((v + 6.f) * scale);
    return min(max(b, 0), BW - 1);
}

// in-block cluster geometry: m, pow2 pad, segment offset
__device__ __forceinline__ void computeOffsets(int* m16, int* p16, int* off16) {
    int tid = threadIdx.x;
    if (tid < 32) {
        int lane = tid;
        int m = 0, p = 0;
        if (lane < KC) {
            m = min(g_cntx[lane], g_cntt[lane]);
            p = (m <= 1) ? m : (1 << (32 - __clz(m - 1)));
        }
        int s = p;
        #pragma unroll
        for (int o = 1; o < 16; o <<= 1) {
            int y = __shfl_up_sync(0xffffffffu, s, o);
            if (lane >= o) s += y;
        }
        if (lane < KC) { m16[lane] = m; p16[lane] = p; off16[lane] = s - p; }
    }
    __syncthreads();
}

// ---------------- assignment + softmax filling + per-chunk counts ----------------
__global__ void assignK(const float* __restrict__ x, const float* __restrict__ C,
                        const int* __restrict__ pr, int N) {
    __shared__ float4 sC[KC * DC / 4];
    __shared__ float  sCC[KC];
    __shared__ float  sFill[KC];
    __shared__ int    sCnt[KC];
    __shared__ int    sCntT[KC];
    int tid = threadIdx.x;
    sC[tid] = ((const float4*)C)[tid];
    if (tid < KC) { sFill[tid] = 0.f; sCnt[tid] = 0; sCntT[tid] = 0; }
    __syncthreads();
    if (tid < KC) {
        float cc = 0.f;
        #pragma unroll
        for (int q = 0; q < DC / 4; q++) {
            float4 c = sC[tid * (DC / 4) + q];
            cc += c.x * c.x + c.y * c.y + c.z * c.z + c.w * c.w;
        }
        sCC[tid] = cc;
    }
    __syncthreads();

    int i = blockIdx.x * blockDim.x + tid;
    bool act = i < N;
    float sc[KC];
    int bk = 0;
    if (act) {
        atomicAdd(&sCntT[pr[i]], 1);
        float acc[KC];
        #pragma unroll
        for (int k = 0; k < KC; k++) acc[k] = 0.f;
        const float4* xr = (const float4*)(x + (size_t)i * DC);
        #pragma unroll
        for (int q = 0; q < DC / 4; q++) {
            float4 v = xr[q];
            #pragma unroll
            for (int k = 0; k < KC; k++) {
                float4 c = sC[k * (DC / 4) + q];
                acc[k] += v.x * c.x + v.y * c.y + v.z * c.z + v.w * c.w;
            }
        }
        float best = FLT_MAX;
        #pragma unroll
        for (int k = 0; k < KC; k++) {
            sc[k] = sCC[k] - 2.f * acc[k];
            if (sc[k] < best) { best = sc[k]; bk = k; }
        }
        g_pred[i] = bk;
        float sum = 0.f;
        #pragma unroll
        for (int k = 0; k < KC; k++) { float e = __expf(-4.f * (sc[k] - best)); sc[k] = e; sum += e; }
        float inv = 1.f / sum;
        #pragma unroll
        for (int k = 0; k < KC; k++) sc[k] *= inv;
        atomicAdd(&sCnt[bk], 1);
    } else {
        #pragma unroll
        for (int k = 0; k < KC; k++) sc[k] = 0.f;
    }
    int lane = tid & 31;
    #pragma unroll
    for (int k = 0; k < KC; k++) {
        float v = sc[k];
        v += __shfl_down_sync(0xffffffffu, v, 16);
        v += __shfl_down_sync(0xffffffffu, v, 8);
        v += __shfl_down_sync(0xffffffffu, v, 4);
        v += __shfl_down_sync(0xffffffffu, v, 2);
        v += __shfl_down_sync(0xffffffffu, v, 1);
        if (lane == 0) atomicAdd(&sFill[k], v);
    }
    __syncthreads();
    if (tid < KC) {
        g_ccx[blockIdx.x * KC + tid] = sCnt[tid];
        g_cct[blockIdx.x * KC + tid] = sCntT[tid];
        g_fillp[blockIdx.x * KC + tid] = sFill[tid];
    }
}

// ---------------- parallel chunk-base scan; zeroes g_loss ----------------
__global__ void scanAK(int nchunk) {
    int b = blockIdx.x;
    int k = b & 15;
    const int* cc = (b < 16) ? g_ccx : g_cct;
    int* cb       = (b < 16) ? g_cbx : g_cbt;
    __shared__ int wtmp[16];
    int tid = threadIdx.x, lane = tid & 31, wid = tid >> 5;
    if (b == 0 && tid == 0) g_loss = 0.f;
    int run = 0;
    for (int c0 = 0; c0 < nchunk; c0 += blockDim.x) {
        int c = c0 + tid;
        int v = (c < nchunk) ? cc[c * KC + k] : 0;
        int s = v;
        #pragma unroll
        for (int o = 1; o < 32; o <<= 1) {
            int y = __shfl_up_sync(0xffffffffu, s, o);
            if (lane >= o) s += y;
        }
        if (lane == 31) wtmp[wid] = s;
        __syncthreads();
        if (wid == 0) {
            int a = (lane < 16) ? wtmp[lane] : 0;
            #pragma unroll
            for (int o = 1; o < 16; o <<= 1) {
                int y = __shfl_up_sync(0xffffffffu, a, o);
                if (lane >= o) a += y;
            }
            if (lane < 16) wtmp[lane] = a;
        }
        __syncthreads();
        int base = (wid ? wtmp[wid - 1] : 0);
        int tot = wtmp[15];
        if (c < nchunk) cb[c * KC + k] = run + base + s - v;
        run += tot;
        __syncthreads();
    }
    if (tid == 0) { if (b < 16) g_cntx[k] = run; else g_cntt[k] = run; }
}

// ---------------- stable scatter (both sources via blockIdx.y) ----------------
__global__ void scatterK(const float* __restrict__ x, const float* __restrict__ tg,
                         const int* __restrict__ pr, int N) {
    __shared__ int wcnt[8][KC];
    __shared__ int m16[KC], p16[KC], off16[KC];
    computeOffsets(m16, p16, off16);
    int isx = (blockIdx.y == 0);
    const float* src = isx ? x : tg;
    const int* pred  = isx ? g_pred : pr;
    const int* cb    = isx ? g_cbx : g_cbt;
    float* dst       = isx ? g_bufx : g_buft;
    int tid = threadIdx.x;
    if (tid < 8 * KC) ((int*)wcnt)[tid] = 0;
    __syncthreads();
    int i = blockIdx.x * blockDim.x + tid;
    int lane = tid & 31, w = tid >> 5;
    int k = 0, lr = 0;
    bool act = i < N;
    unsigned ball = __ballot_sync(0xffffffffu, act);
    if (act) {
        k = pred[i];
        unsigned mm = __match_any_sync(ball, k);
        lr = __popc(mm & ((1u << lane) - 1u));
        if (lane == (int)(__ffs(mm) - 1)) wcnt[w][k] = __popc(mm);
    }
    __syncthreads();
    if (act) {
        int base = cb[blockIdx.x * KC + k];
        #pragma unroll
        for (int ww = 0; ww < 8; ww++)
            if (ww < w) base += wcnt[ww][k];
        int r = base + lr;
        int m = m16[k];
        if (r < m) {
            int P = p16[k];
            float* buf = dst + (size_t)off16[k] * DC + r;
            const float4* s4 = (const float4*)(src + (size_t)i * DC);
            #pragma unroll
            for (int q = 0; q < DC / 4; q++) {
                float4 v = s4[q];
                buf[(size_t)(4 * q + 0) * P] = v.x;
                buf[(size_t)(4 * q + 1) * P] = v.y;
                buf[(size_t)(4 * q + 2) * P] = v.z;
                buf[(size_t)(4 * q + 3) * P] = v.w;
            }
        }
    }
}

// ==================== unified bucket fast/slow W1 ====================

template <int NT, int PER>
__device__ __forceinline__ int scanExInPlace(int* arr, int* wtmp) {
    constexpr int NW = NT / 32;
    int tid = threadIdx.x, lane = tid & 31, wid = tid >> 5;
    int v[PER];
    #pragma unroll
    for (int j = 0; j < PER; j++) v[j] = arr[tid * PER + j];
    int sum = 0;
    #pragma unroll
    for (int j = 0; j < PER; j++) { int t = v[j]; v[j] = sum; sum += t; }
    int inc = sum;
    #pragma unroll
    for (int o = 1; o < 32; o <<= 1) {
        int y = __shfl_up_sync(0xffffffffu, inc, o);
        if (lane >= o) inc += y;
    }
    if (lane == 31) wtmp[wid] = inc;
    __syncthreads();
    if (wid == 0) {
        int a = (lane < NW) ? wtmp[lane] : 0;
        #pragma unroll
        for (int o = 1; o < 32; o <<= 1) {
            int y = __shfl_up_sync(0xffffffffu, a, o);
            if (lane >= o) a += y;
        }
        if (lane < NW) wtmp[lane] = a;
    }
    __syncthreads();
    int base = (wid ? wtmp[wid - 1] : 0) + inc - sum;
    int total = wtmp[NW - 1];
    __syncthreads();
    #pragma unroll
    for (int j = 0; j < PER; j++) arr[tid * PER + j] = base + v[j];
    return total;
}

__global__ void __launch_bounds__(BT) wassU() {
    __shared__ int m16[KC], p16[KC], off16[KC];
    __shared__ int wtmp[32];
    __shared__ float redtmp[32];
    computeOffsets(m16, p16, off16);

    int seg = blockIdx.x;
    int k = seg & 15, d = seg >> 4;     // interleave cluster sizes across waves
    int m = m16[k];
    if (m <= 0) return;
    int twoM = 2 * m;
    int P = p16[k];
    const float* bx = g_bufx + (size_t)off16[k] * DC + (size_t)d * P;
    const float* bt = g_buft + (size_t)off16[k] * DC + (size_t)d * P;

    extern __shared__ __align__(16) int sm[];
    int* cntA = sm;
    int* run0 = sm + BW;
    int* S1   = sm + 2 * BW;
    unsigned* skeys = (unsigned*)(sm + 3 * BW);

    int tid = threadIdx.x;
    const float scale = (float)BW / 12.f;

    bool packed = (twoM < 65536);

    for (int b = tid; b < BW; b += BT) { cntA[b] = 0; run0[b] = 0; }
    __syncthreads();

    // ---------- phase 1: histogram ----------
    if (packed) {
        for (int i = tid; i < m; i += BT) {
            int b = bucketOfBits(normBits(bx[i]), scale);
            atomicAdd((unsigned*)&cntA[b], 0x10001u);
        }
        for (int i = tid; i < m; i += BT) {
            int b = bucketOfBits(normBits(bt[i]), scale);
            atomicAdd((unsigned*)&cntA[b], 0x10000u);
        }
        __syncthreads();
        for (int b = tid; b < BW; b += BT) {
            int h = cntA[b];
            int cnt = h >> 16;
            cntA[b] = cnt;
            run0[b] = 2 * (h & 0xffff) - cnt;
        }
    } else {
        for (int i = tid; i < m; i += BT) {
            int b = bucketOfBits(normBits(bx[i]), scale);
            atomicAdd(&cntA[b], 1); atomicAdd(&run0[b], 1);
        }
        for (int i = tid; i < m; i += BT) {
            int b = bucketOfBits(normBits(bt[i]), scale);
            atomicAdd(&cntA[b], 1); atomicAdd(&run0[b], -1);
        }
    }
    __syncthreads();
    scanExInPlace<BT, BW / BT>(run0, wtmp);
    __syncthreads();

    // slow-bucket compact offsets
    for (int b = tid; b < BW; b += BT) {
        int cnt = cntA[b];
        int r0 = run0[b];
        S1[b] = (r0 <= cnt && r0 >= -cnt) ? cnt : 0;
    }
    __syncthreads();
    int S = scanExInPlace<BT, BW / BT>(S1, wtmp);
    __syncthreads();

    // overwrite dead (fast-bucket) S1 entries with class sentinel:
    // 0x40000000 | 2 for cls=+1 (r0 > cnt), 0x40000000 | 0 for cls=-1
    for (int b = tid; b < BW; b += BT) {
        int cnt = cntA[b];
        int r0 = run0[b];
        if (r0 > cnt)        S1[b] = 0x40000000 | 2;
        else if (r0 < -cnt)  S1[b] = 0x40000000;
    }
    __syncthreads();

    unsigned* kbuf = (S <= SLOTS) ? skeys
                   : (g_scr + (size_t)off16[k] * 2 * DC + (size_t)d * 2 * P);

    // ---------- phase 2: single-LDS fast path; slow items compact-scatter ----------
    float acc = 0.f;
    for (int i = tid; i < m; i += BT) {                 // x items (tag +1)
        unsigned un = normBits(bx[i]);
        int b = bucketOfBits(un, scale);
        int s = S1[b];
        if (s >= 0x40000000) {
            float c = (float)((s & 2) - 1);
            acc -= c * __uint_as_float(un);
        } else {
            int pos = atomicAdd(&S1[b], 1);
            kbuf[pos] = keyFromNorm(un) | 1u;
        }
    }
    for (int i = tid; i < m; i += BT) {                 // t items (tag -1)
        unsigned un = normBits(bt[i]);
        int b = bucketOfBits(un, scale);
        int s = S1[b];
        if (s >= 0x40000000) {
            float c = (float)((s & 2) - 1);
            acc += c * __uint_as_float(un);
        } else {
            int pos = atomicAdd(&S1[b], 1);
            kbuf[pos] = keyFromNorm(un);
        }
    }
    __syncthreads();

    // ---------- phase 3: resolve slow items within their bucket ----------
    for (int idx = tid; idx < S; idx += BT) {
        unsigned kk = kbuf[idx];
        float v = decKey(kk);
        int b = bucketOfBits(__float_as_uint(v), scale);
        int en = S1[b];
        int cnt = cntA[b];
        int st = en - cnt;
        int run = run0[b];
        int mytag = (kk & 1u) ? 1 : -1;
        for (int j = st; j < en; j++) {
            unsigned kj = kbuf[j];
            bool le = (kj < kk) || (kj == kk && j <= idx);
            if (le) run += (kj & 1u) ? 1 : -1;
        }
        acc += v * (fabsf((float)(run - mytag)) - fabsf((float)run));
    }
    __syncthreads();

    // block reduce + accumulate
    int lane = tid & 31, wid = tid >> 5;
    #pragma unroll
    for (int o = 16; o; o >>= 1) acc += __shfl_down_sync(0xffffffffu, acc, o);
    if (lane == 0) redtmp[wid] = acc;
    __syncthreads();
    if (wid == 0) {
        float t = (lane < BT / 32) ? redtmp[lane] : 0.f;
        #pragma unroll
        for (int o = 16; o; o >>= 1) t += __shfl_down_sync(0xffffffffu, t, o);
        if (lane == 0) atomicAdd(&g_loss, t / ((float)m * (float)DC));
    }
}

// ---------------- finalize: reduce fill partials + combine ----------------
__global__ void finalK(const float* __restrict__ ft, float* __restrict__ out,
                       int N, int nchunk) {
    __shared__ float red[256];
    int tid = threadIdx.x;
    int k = tid & 15, g = tid >> 4;
    float s = 0.f;
    for (int c = g; c < nchunk; c += 16) s += g_fillp[c * KC + k];
    red[tid] = s;
    __syncthreads();
    for (int o = 128; o >= 16; o >>= 1) {
        if (tid < o) red[tid] += red[tid + o];
        __syncthreads();
    }
    if (tid == 0) {
        float lf = 0.f;
        for (int kk = 0; kk < KC; kk++) {
            float df = red[kk] / (float)N - ft[kk];
            lf += df * df;
        }
        out[0] = g_loss + lf / (float)KC;
    }
}

extern "C" void kernel_launch(void* const* d_in, const int* in_sizes, int n_in,
                              void* d_out, int out_size) {
    const float* x  = (const float*)d_in[0];
    const float* C  = (const float*)d_in[1];
    const float* ft = (const float*)d_in[2];
    const float* tg = (const float*)d_in[3];
    const int*   pr = (const int*)d_in[4];
    float* out = (float*)d_out;
    int N = in_sizes[0] / DC;
    int nblk = (N + CHUNK - 1) / CHUNK;

    size_t sw = (size_t)(3 * BW + SLOTS) * 4;   // 112 KB -> 2 blocks/SM
    cudaFuncSetAttribute(wassU, cudaFuncAttributeMaxDynamicSharedMemorySize, (int)sw);

    assignK<<<nblk, 256>>>(x, C, pr, N);
    scanAK<<<32, 512>>>(nblk);
    scatterK<<<dim3(nblk, 2), 256>>>(x, tg, pr, N);
    wassU<<<KC * DC, BT, sw>>>();
    finalK<<<1, 256>>>(ft, out, N, nblk);
}